// round 15
// baseline (speedup 1.0000x reference)
#include <cuda_runtime.h>

// Problem constants (fixed by the reference)
#define NN   100000
#define EE   1600000
#define ET   1700000   // EE + NN self loops
#define INC  128
#define OUTC 64
#define KSEL 50000     // ceil(0.5 * NN)
#define NEG  0.2f
#define NB   98        // ceil(NN / 1024) blocks for select count/mask kernels

// ---------------- scratch (device globals; no allocation allowed) ----------
__device__ float g_h[NN * OUTC];     // h = x @ W  (25.6 MB)
__device__ float g_hl[NN];           // h . att[:64]
__device__ float g_hr[NN];           // h . att[64:]
__device__ float g_alpha[ET];        // exp(alpha) -> normalized alpha
__device__ float g_denom[NN];        // segment sum of exp
__device__ float g_asum[NN];         // per-source attention sum
__device__ unsigned char g_mask[NN]; // node_mask
__device__ unsigned int g_h16a[65536];  // histogram of top-16 bits
__device__ unsigned int g_h16b[65536];  // histogram of low-16 bits (within prefix)
__device__ unsigned int g_p16;          // winning top-16 prefix (already <<16)
__device__ unsigned int g_rem16;        // remaining count within prefix
__device__ unsigned int g_T;            // exact 32-bit threshold key
__device__ unsigned int g_need;         // # of ==T keys to keep (lowest index)
__device__ unsigned int g_bcnt[NB];     // per-block equal-to-threshold counts

// ---------------- init (split in 3 so k_gemm is the 4th launch = ncu slot) --
__global__ void k_init0(float* __restrict__ out) {
    int stride = gridDim.x * blockDim.x;
    int i0 = blockIdx.x * blockDim.x + threadIdx.x;
    float4* o4 = (float4*)out;
    float4 z4 = make_float4(0.f, 0.f, 0.f, 0.f);
    for (int j = i0; j < NN * OUTC / 4; j += stride) o4[j] = z4;
}
__global__ void k_init1() {
    int stride = gridDim.x * blockDim.x;
    int i0 = blockIdx.x * blockDim.x + threadIdx.x;
    for (int j = i0; j < NN; j += stride) {
        g_denom[j] = 0.f;
        g_asum[j]  = 0.f;
    }
}
__global__ void k_init2() {
    int stride = gridDim.x * blockDim.x;
    int i0 = blockIdx.x * blockDim.x + threadIdx.x;
    for (int j = i0; j < 65536; j += stride) {
        g_h16a[j] = 0;
        g_h16b[j] = 0;
    }
}

// ---------------- GEMM + fused att projections -------------------------------
// 128 threads = 4 warps; 32 nodes/block, 8 nodes per warp; lane = channel pair.
// W read (2 wavefronts/k) now amortizes over 8 nodes: 2 wf per 16 FFMA instrs
// instead of 3 wf per 8 -> LDS pressure drops ~1.5x per FMA.
__global__ __launch_bounds__(128) void k_gemm(const float* __restrict__ x,
                                              const float* __restrict__ w,
                                              const float* __restrict__ att) {
    __shared__ float2 sW[INC * 32];   // 32 KB  [k][lane]
    __shared__ float4 sx[32][32];     // 16 KB  [node][k4]
    int tid  = threadIdx.x;
    int lane = tid & 31;
    int wid  = tid >> 5;              // 0..3

    const float2* w2 = (const float2*)w;
    for (int i = tid; i < INC * 32; i += 128) sW[i] = w2[i];

    int nb = blockIdx.x * 32;
    const float4* x4 = (const float4*)x;
    for (int i = tid; i < 32 * 32; i += 128) {
        int node = i >> 5, k4 = i & 31;
        int n = nb + node;
        sx[node][k4] = (n < NN) ? x4[(size_t)n * 32 + k4] : make_float4(0.f, 0.f, 0.f, 0.f);
    }
    __syncthreads();

    int n0 = wid * 8;                 // 8 nodes per warp
    float a0[8] = {0.f, 0.f, 0.f, 0.f, 0.f, 0.f, 0.f, 0.f};
    float a1[8] = {0.f, 0.f, 0.f, 0.f, 0.f, 0.f, 0.f, 0.f};
    #pragma unroll 2
    for (int k4 = 0; k4 < 32; k4++) {
        float2 w0 = sW[(k4 * 4 + 0) * 32 + lane];
        float2 w1 = sW[(k4 * 4 + 1) * 32 + lane];
        float2 wv2 = sW[(k4 * 4 + 2) * 32 + lane];
        float2 w3 = sW[(k4 * 4 + 3) * 32 + lane];
        #pragma unroll
        for (int j = 0; j < 8; j++) {
            float4 xv = sx[n0 + j][k4];
            a0[j] = fmaf(xv.x, w0.x, a0[j]);  a1[j] = fmaf(xv.x, w0.y, a1[j]);
            a0[j] = fmaf(xv.y, w1.x, a0[j]);  a1[j] = fmaf(xv.y, w1.y, a1[j]);
            a0[j] = fmaf(xv.z, wv2.x, a0[j]); a1[j] = fmaf(xv.z, wv2.y, a1[j]);
            a0[j] = fmaf(xv.w, w3.x, a0[j]);  a1[j] = fmaf(xv.w, w3.y, a1[j]);
        }
    }

    float2 atL = ((const float2*)att)[lane];
    float2 atR = ((const float2*)att)[32 + lane];
    #pragma unroll
    for (int j = 0; j < 8; j++) {
        int n = nb + n0 + j;
        if (n >= NN) continue;
        ((float2*)g_h)[(size_t)n * 32 + lane] = make_float2(a0[j], a1[j]);
        float pl = a0[j] * atL.x + a1[j] * atL.y;
        float pr = a0[j] * atR.x + a1[j] * atR.y;
        #pragma unroll
        for (int o = 16; o > 0; o >>= 1) {
            pl += __shfl_down_sync(0xFFFFFFFFu, pl, o);
            pr += __shfl_down_sync(0xFFFFFFFFu, pr, o);
        }
        if (lane == 0) { g_hl[n] = pl; g_hr[n] = pr; }
    }
}

// ---------------- edge pass A: 4 edges/thread, alpha->exp + denom -----------
// (max-subtraction skipped: softmax shift-invariant; alpha bounded ~|10|)
__global__ __launch_bounds__(256) void k_edgeA(const int* __restrict__ src,
                                               const int* __restrict__ tgt) {
    int p = blockIdx.x * blockDim.x + threadIdx.x;   // pack of 4 edges
    int e0 = p * 4;
    if (e0 >= ET) return;
    int s[4], t[4];
    if (e0 < EE) {   // EE % 4 == 0: packs never straddle the boundary
        int4 s4 = ((const int4*)src)[p];
        int4 t4 = ((const int4*)tgt)[p];
        s[0] = s4.x; s[1] = s4.y; s[2] = s4.z; s[3] = s4.w;
        t[0] = t4.x; t[1] = t4.y; t[2] = t4.z; t[3] = t4.w;
    } else {
        int b = e0 - EE;
        #pragma unroll
        for (int i = 0; i < 4; i++) { s[i] = b + i; t[i] = b + i; }
    }
    float hlv[4], hrv[4];
    #pragma unroll
    for (int i = 0; i < 4; i++) hlv[i] = g_hl[t[i]];
    #pragma unroll
    for (int i = 0; i < 4; i++) hrv[i] = g_hr[s[i]];
    float av[4];
    #pragma unroll
    for (int i = 0; i < 4; i++) {
        float al = hlv[i] + hrv[i];
        al = al > 0.f ? al : NEG * al;
        av[i] = __expf(al);
    }
    ((float4*)g_alpha)[p] = make_float4(av[0], av[1], av[2], av[3]);
    #pragma unroll
    for (int i = 0; i < 4; i++) atomicAdd(g_denom + t[i], av[i]);
}

// ---------------- edge pass B: 4 edges/thread, normalize + asum -------------
__global__ __launch_bounds__(256) void k_edgeB(const int* __restrict__ src,
                                               const int* __restrict__ tgt) {
    int p = blockIdx.x * blockDim.x + threadIdx.x;
    int e0 = p * 4;
    if (e0 >= ET) return;
    int s[4], t[4];
    if (e0 < EE) {
        int4 s4 = ((const int4*)src)[p];
        int4 t4 = ((const int4*)tgt)[p];
        s[0] = s4.x; s[1] = s4.y; s[2] = s4.z; s[3] = s4.w;
        t[0] = t4.x; t[1] = t4.y; t[2] = t4.z; t[3] = t4.w;
    } else {
        int b = e0 - EE;
        #pragma unroll
        for (int i = 0; i < 4; i++) { s[i] = b + i; t[i] = b + i; }
    }
    float4 a4 = ((const float4*)g_alpha)[p];
    float av[4] = {a4.x, a4.y, a4.z, a4.w};
    float dn[4];
    #pragma unroll
    for (int i = 0; i < 4; i++) dn[i] = g_denom[t[i]];
    #pragma unroll
    for (int i = 0; i < 4; i++) av[i] = __fdividef(av[i], dn[i] + 1e-16f);
    ((float4*)g_alpha)[p] = make_float4(av[0], av[1], av[2], av[3]);
    #pragma unroll
    for (int i = 0; i < 4; i++) atomicAdd(g_asum + s[i], av[i]);
}

// ---------------- exact top-k: 16-bit two-pass radix, no grid barriers ------
__device__ __forceinline__ unsigned int ordkey(float f) {
    unsigned int u = __float_as_uint(f);
    return (u & 0x80000000u) ? ~u : (u | 0x80000000u);
}

__global__ __launch_bounds__(1024) void k_histA() {
    int n = blockIdx.x * 1024 + threadIdx.x;
    if (n < NN) atomicAdd(&g_h16a[ordkey(g_asum[n]) >> 16], 1u);
}

__global__ __launch_bounds__(1024) void k_histB() {
    int n = blockIdx.x * 1024 + threadIdx.x;
    if (n >= NN) return;
    unsigned int u = ordkey(g_asum[n]);
    if ((u & 0xFFFF0000u) == g_p16) atomicAdd(&g_h16b[u & 0xFFFFu], 1u);
}

// Single-block parallel selection over a 65536-bin histogram.
// phase 0: hist=g_h16a, K=KSEL    -> g_p16, g_rem16
// phase 1: hist=g_h16b, K=g_rem16 -> g_T, g_need
__global__ __launch_bounds__(1024) void k_scan(int phase) {
    __shared__ unsigned int ss[1024];
    __shared__ unsigned int gsfx[256];
    __shared__ unsigned int hs[256];
    __shared__ unsigned int s_G, s_remG;
    const unsigned int* hist = phase ? g_h16b : g_h16a;
    unsigned int K = phase ? g_rem16 : (unsigned int)KSEL;
    int tid = threadIdx.x;

    unsigned int cs = 0;
    #pragma unroll 8
    for (int i = 0; i < 64; i++) cs += hist[tid * 64 + i];
    ss[tid] = cs;
    __syncthreads();
    if (tid < 256) gsfx[tid] = ss[4 * tid] + ss[4 * tid + 1] + ss[4 * tid + 2] + ss[4 * tid + 3];
    __syncthreads();
    #pragma unroll
    for (int off = 1; off < 256; off <<= 1) {
        unsigned int v = 0;
        if (tid < 256) { v = gsfx[tid]; if (tid + off < 256) v += gsfx[tid + off]; }
        __syncthreads();
        if (tid < 256) gsfx[tid] = v;
        __syncthreads();
    }
    if (tid < 256) {
        unsigned int S = gsfx[tid];
        unsigned int Sn = (tid < 255) ? gsfx[tid + 1] : 0u;
        if (S >= K && Sn < K) { s_G = tid; s_remG = K - Sn; }
    }
    __syncthreads();
    unsigned int G = s_G, remG = s_remG;
    if (tid < 256) hs[tid] = hist[G * 256 + tid];
    __syncthreads();
    #pragma unroll
    for (int off = 1; off < 256; off <<= 1) {
        unsigned int v = 0;
        if (tid < 256) { v = hs[tid]; if (tid + off < 256) v += hs[tid + off]; }
        __syncthreads();
        if (tid < 256) hs[tid] = v;
        __syncthreads();
    }
    if (tid < 256) {
        unsigned int S = hs[tid];
        unsigned int Sn = (tid < 255) ? hs[tid + 1] : 0u;
        if (S >= remG && Sn < remG) {
            unsigned int digit = G * 256 + tid;
            unsigned int rem = remG - Sn;
            if (phase == 0) { g_p16 = digit << 16; g_rem16 = rem; }
            else            { g_T = g_p16 | digit; g_need = rem; }
        }
    }
}

__global__ __launch_bounds__(1024) void k_cnt() {
    __shared__ unsigned int wsum[32];
    int tid = threadIdx.x, b = blockIdx.x;
    int n = b * 1024 + tid;
    unsigned int T = g_T;
    unsigned int eq = (n < NN && ordkey(g_asum[n]) == T) ? 1u : 0u;
    unsigned int bal = __ballot_sync(0xFFFFFFFFu, eq);
    if ((tid & 31) == 0) wsum[tid >> 5] = __popc(bal);
    __syncthreads();
    if (tid == 0) {
        unsigned int tot = 0;
        #pragma unroll
        for (int i = 0; i < 32; i++) tot += wsum[i];
        g_bcnt[b] = tot;
    }
}

// Final mask with stable tie break; fused node_mask output.
__global__ __launch_bounds__(1024) void k_maskk(float* __restrict__ nmask, int wm) {
    __shared__ unsigned int wsum[32], woff[32];
    __shared__ unsigned int sb[NB];
    __shared__ unsigned int s_boff;
    int tid = threadIdx.x, b = blockIdx.x;
    int n = b * 1024 + tid;
    unsigned int T = g_T, need = g_need;
    unsigned int u = (n < NN) ? ordkey(g_asum[n]) : 0u;
    unsigned int eq = (n < NN && u == T) ? 1u : 0u;
    unsigned int bal = __ballot_sync(0xFFFFFFFFu, eq);
    unsigned int lanePre = __popc(bal & ((1u << (tid & 31)) - 1u));
    int w = tid >> 5;
    if ((tid & 31) == 0) wsum[w] = __popc(bal);
    if (tid < NB) sb[tid] = g_bcnt[tid];
    __syncthreads();
    if (tid == 0) {
        unsigned int acc = 0;
        #pragma unroll
        for (int i = 0; i < 32; i++) { woff[i] = acc; acc += wsum[i]; }
        unsigned int boff = 0;
        for (int i = 0; i < b; i++) boff += sb[i];
        s_boff = boff;
    }
    __syncthreads();
    if (n < NN) {
        unsigned int rank = s_boff + woff[w] + lanePre;
        bool sel = (u > T) || (eq && rank < need);
        g_mask[n] = sel ? 1 : 0;
        if (wm) nmask[n] = sel ? 1.f : 0.f;
    }
}

// ---------------- aggregation: out[t] += alpha * h[s] (R8-proven) -----------
__global__ __launch_bounds__(256) void k_aggr(const int* __restrict__ src,
                                              const int* __restrict__ tgt,
                                              float* __restrict__ out,
                                              float* __restrict__ emask, int wm) {
    int e = blockIdx.x * 16 + (threadIdx.x >> 4);
    if (e >= ET) return;
    int l = threadIdx.x & 15;
    int s, t;
    if (e < EE) { s = src[e]; t = tgt[e]; } else { s = t = e - EE; }
    bool keep = g_mask[s] && g_mask[t];
    if (wm && l == 0) emask[e] = keep ? 1.f : 0.f;
    if (!keep) return;
    float an = g_alpha[e];
    float4 hv = ((const float4*)g_h)[(size_t)s * 16 + l];
    float* dst = out + (size_t)t * OUTC + l * 4;
    asm volatile("red.global.add.v4.f32 [%0], {%1, %2, %3, %4};"
                 :: "l"(dst), "f"(an * hv.x), "f"(an * hv.y),
                    "f"(an * hv.z), "f"(an * hv.w)
                 : "memory");
}

// ---------------- launch ----------------------------------------------------
extern "C" void kernel_launch(void* const* d_in, const int* in_sizes, int n_in,
                              void* d_out, int out_size) {
    const float* x   = (const float*)d_in[0];   // [NN, INC]
    const float* w   = (const float*)d_in[1];   // [INC, OUTC]
    const float* att = (const float*)d_in[2];   // [1, 2*OUTC]
    const int*   ei  = (const int*)d_in[3];     // [2, EE]
    const int*   src = ei;
    const int*   tgt = ei + EE;
    float* out = (float*)d_out;

    int wm = (out_size >= NN * OUTC + ET + NN) ? 1 : 0;
    float* emask = out + NN * OUTC;
    float* nmask = emask + ET;

    k_init0<<<1024, 256>>>(out);     // 1st launch
    k_init1<<<256, 256>>>();         // 2nd
    k_init2<<<256, 256>>>();         // 3rd
    k_gemm<<<(NN + 31) / 32, 128>>>(x, w, att);   // 4th = ncu capture slot
    int pb = (ET / 4 + 255) / 256;
    k_edgeA<<<pb, 256>>>(src, tgt);
    k_edgeB<<<pb, 256>>>(src, tgt);
    k_histA<<<NB, 1024>>>();
    k_scan<<<1, 1024>>>(0);
    k_histB<<<NB, 1024>>>();
    k_scan<<<1, 1024>>>(1);
    k_cnt<<<NB, 1024>>>();
    k_maskk<<<NB, 1024>>>(nmask, wm);
    k_aggr<<<(ET + 15) / 16, 256>>>(src, tgt, out, emask, wm);
}

// round 16
// speedup vs baseline: 1.0014x; 1.0014x over previous
#include <cuda_runtime.h>

// Problem constants (fixed by the reference)
#define NN   100000
#define EE   1600000
#define ET   1700000   // EE + NN self loops
#define INC  128
#define OUTC 64
#define KSEL 50000     // ceil(0.5 * NN)
#define NEG  0.2f
#define NB   98        // ceil(NN / 1024) blocks for select count/mask kernels

// ---------------- scratch (device globals; no allocation allowed) ----------
__device__ float g_h[NN * OUTC];     // h = x @ W  (25.6 MB)
__device__ float g_hl[NN];           // h . att[:64]
__device__ float g_hr[NN];           // h . att[64:]
__device__ float g_alpha[ET];        // exp(alpha)  (normalization applied on use)
__device__ float g_denom[NN];        // segment sum of exp
__device__ float g_asum[NN];         // per-source attention sum
__device__ unsigned char g_mask[NN]; // node_mask
__device__ unsigned int g_h16a[65536];  // histogram of top-16 bits
__device__ unsigned int g_h16b[65536];  // histogram of low-16 bits (within prefix)
__device__ unsigned int g_p16;          // winning top-16 prefix (already <<16)
__device__ unsigned int g_rem16;        // remaining count within prefix
__device__ unsigned int g_T;            // exact 32-bit threshold key
__device__ unsigned int g_need;         // # of ==T keys to keep (lowest index)
__device__ unsigned int g_bcnt[NB];     // per-block equal-to-threshold counts

// ---------------- init kernels ----------------------------------------------
__global__ void k_init0(float* __restrict__ out) {
    int stride = gridDim.x * blockDim.x;
    int i0 = blockIdx.x * blockDim.x + threadIdx.x;
    float4* o4 = (float4*)out;
    float4 z4 = make_float4(0.f, 0.f, 0.f, 0.f);
    for (int j = i0; j < NN * OUTC / 4; j += stride) o4[j] = z4;
}
__global__ void k_init1() {
    int stride = gridDim.x * blockDim.x;
    int i0 = blockIdx.x * blockDim.x + threadIdx.x;
    for (int j = i0; j < NN; j += stride) {
        g_denom[j] = 0.f;
        g_asum[j]  = 0.f;
    }
}
__global__ void k_init2() {
    int stride = gridDim.x * blockDim.x;
    int i0 = blockIdx.x * blockDim.x + threadIdx.x;
    for (int j = i0; j < 65536; j += stride) {
        g_h16a[j] = 0;
        g_h16b[j] = 0;
    }
}

// ---------------- GEMM + fused att projections (R8/R13-proven, FROZEN) ------
__global__ __launch_bounds__(256) void k_gemm(const float* __restrict__ x,
                                              const float* __restrict__ w,
                                              const float* __restrict__ att) {
    __shared__ float2 sW[INC * 32];   // [k][lane]
    __shared__ float4 sx[32][32];     // [node][k4]
    int tid  = threadIdx.x;
    int lane = tid & 31;
    int wid  = tid >> 5;

    const float2* w2 = (const float2*)w;
    for (int i = tid; i < INC * 32; i += 256) sW[i] = w2[i];

    int nb = blockIdx.x * 32;
    const float4* x4 = (const float4*)x;
    for (int i = tid; i < 32 * 32; i += 256) {
        int node = i >> 5, k4 = i & 31;
        int n = nb + node;
        sx[node][k4] = (n < NN) ? x4[(size_t)n * 32 + k4] : make_float4(0.f, 0.f, 0.f, 0.f);
    }
    __syncthreads();

    int n0 = wid * 4;
    float a0[4] = {0.f, 0.f, 0.f, 0.f};
    float a1[4] = {0.f, 0.f, 0.f, 0.f};
    #pragma unroll 4
    for (int k4 = 0; k4 < 32; k4++) {
        float2 w0 = sW[(k4 * 4 + 0) * 32 + lane];
        float2 w1 = sW[(k4 * 4 + 1) * 32 + lane];
        float2 wv2 = sW[(k4 * 4 + 2) * 32 + lane];
        float2 w3 = sW[(k4 * 4 + 3) * 32 + lane];
        #pragma unroll
        for (int j = 0; j < 4; j++) {
            float4 xv = sx[n0 + j][k4];
            a0[j] = fmaf(xv.x, w0.x, a0[j]);  a1[j] = fmaf(xv.x, w0.y, a1[j]);
            a0[j] = fmaf(xv.y, w1.x, a0[j]);  a1[j] = fmaf(xv.y, w1.y, a1[j]);
            a0[j] = fmaf(xv.z, wv2.x, a0[j]); a1[j] = fmaf(xv.z, wv2.y, a1[j]);
            a0[j] = fmaf(xv.w, w3.x, a0[j]);  a1[j] = fmaf(xv.w, w3.y, a1[j]);
        }
    }

    float2 atL = ((const float2*)att)[lane];
    float2 atR = ((const float2*)att)[32 + lane];
    #pragma unroll
    for (int j = 0; j < 4; j++) {
        int n = nb + n0 + j;
        if (n >= NN) continue;
        ((float2*)g_h)[(size_t)n * 32 + lane] = make_float2(a0[j], a1[j]);
        float pl = a0[j] * atL.x + a1[j] * atL.y;
        float pr = a0[j] * atR.x + a1[j] * atR.y;
        #pragma unroll
        for (int o = 16; o > 0; o >>= 1) {
            pl += __shfl_down_sync(0xFFFFFFFFu, pl, o);
            pr += __shfl_down_sync(0xFFFFFFFFu, pr, o);
        }
        if (lane == 0) { g_hl[n] = pl; g_hr[n] = pr; }
    }
}

// ---------------- edge pass A: 4 edges/thread, alpha->exp + denom -----------
// (max-subtraction skipped: softmax shift-invariant; alpha bounded ~|10|)
__global__ __launch_bounds__(256) void k_edgeA(const int* __restrict__ src,
                                               const int* __restrict__ tgt) {
    int p = blockIdx.x * blockDim.x + threadIdx.x;   // pack of 4 edges
    int e0 = p * 4;
    if (e0 >= ET) return;
    int s[4], t[4];
    if (e0 < EE) {   // EE % 4 == 0: packs never straddle the boundary
        int4 s4 = ((const int4*)src)[p];
        int4 t4 = ((const int4*)tgt)[p];
        s[0] = s4.x; s[1] = s4.y; s[2] = s4.z; s[3] = s4.w;
        t[0] = t4.x; t[1] = t4.y; t[2] = t4.z; t[3] = t4.w;
    } else {
        int b = e0 - EE;
        #pragma unroll
        for (int i = 0; i < 4; i++) { s[i] = b + i; t[i] = b + i; }
    }
    float hlv[4], hrv[4];
    #pragma unroll
    for (int i = 0; i < 4; i++) hlv[i] = g_hl[t[i]];
    #pragma unroll
    for (int i = 0; i < 4; i++) hrv[i] = g_hr[s[i]];
    float av[4];
    #pragma unroll
    for (int i = 0; i < 4; i++) {
        float al = hlv[i] + hrv[i];
        al = al > 0.f ? al : NEG * al;
        av[i] = __expf(al);
    }
    ((float4*)g_alpha)[p] = make_float4(av[0], av[1], av[2], av[3]);
    #pragma unroll
    for (int i = 0; i < 4; i++) atomicAdd(g_denom + t[i], av[i]);
}

// ---------------- edge pass B: normalize (no writeback) + asum --------------
__global__ __launch_bounds__(256) void k_edgeB(const int* __restrict__ src,
                                               const int* __restrict__ tgt) {
    int p = blockIdx.x * blockDim.x + threadIdx.x;
    int e0 = p * 4;
    if (e0 >= ET) return;
    int s[4], t[4];
    if (e0 < EE) {
        int4 s4 = ((const int4*)src)[p];
        int4 t4 = ((const int4*)tgt)[p];
        s[0] = s4.x; s[1] = s4.y; s[2] = s4.z; s[3] = s4.w;
        t[0] = t4.x; t[1] = t4.y; t[2] = t4.z; t[3] = t4.w;
    } else {
        int b = e0 - EE;
        #pragma unroll
        for (int i = 0; i < 4; i++) { s[i] = b + i; t[i] = b + i; }
    }
    float4 a4 = ((const float4*)g_alpha)[p];
    float av[4] = {a4.x, a4.y, a4.z, a4.w};
    float dn[4];
    #pragma unroll
    for (int i = 0; i < 4; i++) dn[i] = g_denom[t[i]];
    #pragma unroll
    for (int i = 0; i < 4; i++) av[i] = __fdividef(av[i], dn[i] + 1e-16f);
    // g_alpha keeps exp(); aggregation recomputes the identical division.
    #pragma unroll
    for (int i = 0; i < 4; i++) atomicAdd(g_asum + s[i], av[i]);
}

// ---------------- exact top-k: 16-bit two-pass radix, no grid barriers ------
__device__ __forceinline__ unsigned int ordkey(float f) {
    unsigned int u = __float_as_uint(f);
    return (u & 0x80000000u) ? ~u : (u | 0x80000000u);
}

__global__ __launch_bounds__(1024) void k_histA() {
    int n = blockIdx.x * 1024 + threadIdx.x;
    if (n < NN) atomicAdd(&g_h16a[ordkey(g_asum[n]) >> 16], 1u);
}

__global__ __launch_bounds__(1024) void k_histB() {
    int n = blockIdx.x * 1024 + threadIdx.x;
    if (n >= NN) return;
    unsigned int u = ordkey(g_asum[n]);
    if ((u & 0xFFFF0000u) == g_p16) atomicAdd(&g_h16b[u & 0xFFFFu], 1u);
}

// Single-block parallel selection over a 65536-bin histogram.
// phase 0: hist=g_h16a, K=KSEL    -> g_p16, g_rem16
// phase 1: hist=g_h16b, K=g_rem16 -> g_T, g_need
__global__ __launch_bounds__(1024) void k_scan(int phase) {
    __shared__ unsigned int ss[1024];
    __shared__ unsigned int gsfx[256];
    __shared__ unsigned int hs[256];
    __shared__ unsigned int s_G, s_remG;
    const unsigned int* hist = phase ? g_h16b : g_h16a;
    unsigned int K = phase ? g_rem16 : (unsigned int)KSEL;
    int tid = threadIdx.x;

    unsigned int cs = 0;
    #pragma unroll 8
    for (int i = 0; i < 64; i++) cs += hist[tid * 64 + i];
    ss[tid] = cs;
    __syncthreads();
    if (tid < 256) gsfx[tid] = ss[4 * tid] + ss[4 * tid + 1] + ss[4 * tid + 2] + ss[4 * tid + 3];
    __syncthreads();
    #pragma unroll
    for (int off = 1; off < 256; off <<= 1) {
        unsigned int v = 0;
        if (tid < 256) { v = gsfx[tid]; if (tid + off < 256) v += gsfx[tid + off]; }
        __syncthreads();
        if (tid < 256) gsfx[tid] = v;
        __syncthreads();
    }
    if (tid < 256) {
        unsigned int S = gsfx[tid];
        unsigned int Sn = (tid < 255) ? gsfx[tid + 1] : 0u;
        if (S >= K && Sn < K) { s_G = tid; s_remG = K - Sn; }
    }
    __syncthreads();
    unsigned int G = s_G, remG = s_remG;
    if (tid < 256) hs[tid] = hist[G * 256 + tid];
    __syncthreads();
    #pragma unroll
    for (int off = 1; off < 256; off <<= 1) {
        unsigned int v = 0;
        if (tid < 256) { v = hs[tid]; if (tid + off < 256) v += hs[tid + off]; }
        __syncthreads();
        if (tid < 256) hs[tid] = v;
        __syncthreads();
    }
    if (tid < 256) {
        unsigned int S = hs[tid];
        unsigned int Sn = (tid < 255) ? hs[tid + 1] : 0u;
        if (S >= remG && Sn < remG) {
            unsigned int digit = G * 256 + tid;
            unsigned int rem = remG - Sn;
            if (phase == 0) { g_p16 = digit << 16; g_rem16 = rem; }
            else            { g_T = g_p16 | digit; g_need = rem; }
        }
    }
}

__global__ __launch_bounds__(1024) void k_cnt() {
    __shared__ unsigned int wsum[32];
    int tid = threadIdx.x, b = blockIdx.x;
    int n = b * 1024 + tid;
    unsigned int T = g_T;
    unsigned int eq = (n < NN && ordkey(g_asum[n]) == T) ? 1u : 0u;
    unsigned int bal = __ballot_sync(0xFFFFFFFFu, eq);
    if ((tid & 31) == 0) wsum[tid >> 5] = __popc(bal);
    __syncthreads();
    if (tid == 0) {
        unsigned int tot = 0;
        #pragma unroll
        for (int i = 0; i < 32; i++) tot += wsum[i];
        g_bcnt[b] = tot;
    }
}

// Final mask with stable tie break; fused node_mask output.
__global__ __launch_bounds__(1024) void k_maskk(float* __restrict__ nmask, int wm) {
    __shared__ unsigned int wsum[32], woff[32];
    __shared__ unsigned int sb[NB];
    __shared__ unsigned int s_boff;
    int tid = threadIdx.x, b = blockIdx.x;
    int n = b * 1024 + tid;
    unsigned int T = g_T, need = g_need;
    unsigned int u = (n < NN) ? ordkey(g_asum[n]) : 0u;
    unsigned int eq = (n < NN && u == T) ? 1u : 0u;
    unsigned int bal = __ballot_sync(0xFFFFFFFFu, eq);
    unsigned int lanePre = __popc(bal & ((1u << (tid & 31)) - 1u));
    int w = tid >> 5;
    if ((tid & 31) == 0) wsum[w] = __popc(bal);
    if (tid < NB) sb[tid] = g_bcnt[tid];
    __syncthreads();
    if (tid == 0) {
        unsigned int acc = 0;
        #pragma unroll
        for (int i = 0; i < 32; i++) { woff[i] = acc; acc += wsum[i]; }
        unsigned int boff = 0;
        for (int i = 0; i < b; i++) boff += sb[i];
        s_boff = boff;
    }
    __syncthreads();
    if (n < NN) {
        unsigned int rank = s_boff + woff[w] + lanePre;
        bool sel = (u > T) || (eq && rank < need);
        g_mask[n] = sel ? 1 : 0;
        if (wm) nmask[n] = sel ? 1.f : 0.f;
    }
}

// ---------------- emask: 4 edges/thread, coalesced float4 stores -------------
__global__ __launch_bounds__(256) void k_emask(const int* __restrict__ src,
                                               const int* __restrict__ tgt,
                                               float* __restrict__ emask) {
    int p = blockIdx.x * 256 + threadIdx.x;   // pack of 4 edges
    int e0 = p * 4;
    if (e0 >= ET) return;
    float m[4];
    if (e0 < EE) {
        int4 s4 = ((const int4*)src)[p];
        int4 t4 = ((const int4*)tgt)[p];
        m[0] = (g_mask[s4.x] && g_mask[t4.x]) ? 1.f : 0.f;
        m[1] = (g_mask[s4.y] && g_mask[t4.y]) ? 1.f : 0.f;
        m[2] = (g_mask[s4.z] && g_mask[t4.z]) ? 1.f : 0.f;
        m[3] = (g_mask[s4.w] && g_mask[t4.w]) ? 1.f : 0.f;
    } else {
        int b = e0 - EE;
        #pragma unroll
        for (int i = 0; i < 4; i++) m[i] = g_mask[b + i] ? 1.f : 0.f;
    }
    ((float4*)emask)[p] = make_float4(m[0], m[1], m[2], m[3]);
}

// ---------------- aggregation: out[t] += alpha_norm * h[s] -------------------
// Half-warp per edge; normalization recomputed (identical __fdividef).
__global__ __launch_bounds__(256) void k_aggr(const int* __restrict__ src,
                                              const int* __restrict__ tgt,
                                              float* __restrict__ out) {
    int e = blockIdx.x * 16 + (threadIdx.x >> 4);
    if (e >= ET) return;
    int l = threadIdx.x & 15;
    int s, t;
    if (e < EE) { s = src[e]; t = tgt[e]; } else { s = t = e - EE; }
    if (!(g_mask[s] && g_mask[t])) return;
    float an = __fdividef(g_alpha[e], g_denom[t] + 1e-16f);
    float4 hv = ((const float4*)g_h)[(size_t)s * 16 + l];
    float* dst = out + (size_t)t * OUTC + l * 4;
    asm volatile("red.global.add.v4.f32 [%0], {%1, %2, %3, %4};"
                 :: "l"(dst), "f"(an * hv.x), "f"(an * hv.y),
                    "f"(an * hv.z), "f"(an * hv.w)
                 : "memory");
}

// ---------------- launch ----------------------------------------------------
extern "C" void kernel_launch(void* const* d_in, const int* in_sizes, int n_in,
                              void* d_out, int out_size) {
    const float* x   = (const float*)d_in[0];   // [NN, INC]
    const float* w   = (const float*)d_in[1];   // [INC, OUTC]
    const float* att = (const float*)d_in[2];   // [1, 2*OUTC]
    const int*   ei  = (const int*)d_in[3];     // [2, EE]
    const int*   src = ei;
    const int*   tgt = ei + EE;
    float* out = (float*)d_out;

    int wm = (out_size >= NN * OUTC + ET + NN) ? 1 : 0;
    float* emask = out + NN * OUTC;
    float* nmask = emask + ET;

    int pb = (ET / 4 + 255) / 256;
    k_init1<<<256, 256>>>();                       // 1st: denom/asum zero
    k_gemm<<<(NN + 31) / 32, 256>>>(x, w, att);    // 2nd
    k_init0<<<1024, 256>>>(out);                   // 3rd: out zero
    k_edgeA<<<pb, 256>>>(src, tgt);                // 4th = ncu capture slot
    k_edgeB<<<pb, 256>>>(src, tgt);
    k_init2<<<256, 256>>>();                       // hist zero (before histA)
    k_histA<<<NB, 1024>>>();
    k_scan<<<1, 1024>>>(0);
    k_histB<<<NB, 1024>>>();
    k_scan<<<1, 1024>>>(1);
    k_cnt<<<NB, 1024>>>();
    k_maskk<<<NB, 1024>>>(nmask, wm);
    if (wm) k_emask<<<pb, 256>>>(src, tgt, emask);
    k_aggr<<<(ET + 15) / 16, 256>>>(src, tgt, out);
}

// round 17
// speedup vs baseline: 1.0971x; 1.0956x over previous
#include <cuda_runtime.h>

// Problem constants (fixed by the reference)
#define NN   100000
#define EE   1600000
#define ET   1700000   // EE + NN self loops
#define INC  128
#define OUTC 64
#define KSEL 50000     // ceil(0.5 * NN)
#define NEG  0.2f
#define NB   98        // ceil(NN / 1024) blocks for node-grid kernels

// ---------------- scratch (device globals; no allocation allowed) ----------
__device__ float g_h[NN * OUTC];     // h = x @ W  (25.6 MB)
__device__ float g_hl[NN];           // h . att[:64]
__device__ float g_hr[NN];           // h . att[64:]
__device__ float g_alpha[ET];        // exp(alpha) -> normalized alpha
__device__ float g_denom[NN];        // segment sum of exp
__device__ float g_asum[NN];         // per-source attention sum
__device__ unsigned char g_mask[NN]; // node_mask
__device__ unsigned int g_h16a[65536];  // histogram of top-16 bits
__device__ unsigned int g_p16;          // winning top-16 prefix (already <<16)
__device__ unsigned int g_rem16;        // # to select inside the boundary bin
__device__ unsigned int g_cand_n;       // boundary-bin candidate count
__device__ unsigned int g_ck[NN];       // candidate full keys
__device__ int          g_ci[NN];       // candidate node indices

// ---------------- init (split so k_gemm stays the 4th launch = ncu slot) ----
__global__ void k_init0(float* __restrict__ out) {
    int stride = gridDim.x * blockDim.x;
    int i0 = blockIdx.x * blockDim.x + threadIdx.x;
    float4* o4 = (float4*)out;
    float4 z4 = make_float4(0.f, 0.f, 0.f, 0.f);
    for (int j = i0; j < NN * OUTC / 4; j += stride) o4[j] = z4;
}
__global__ void k_init1() {
    int stride = gridDim.x * blockDim.x;
    int i0 = blockIdx.x * blockDim.x + threadIdx.x;
    for (int j = i0; j < NN; j += stride) {
        g_denom[j] = 0.f;
        g_asum[j]  = 0.f;
    }
    if (i0 == 0) g_cand_n = 0;
}
__global__ void k_init2() {
    int stride = gridDim.x * blockDim.x;
    int i0 = blockIdx.x * blockDim.x + threadIdx.x;
    for (int j = i0; j < 65536; j += stride) g_h16a[j] = 0;
}

// ---------------- GEMM + fused att projections (R8/R13-proven, FROZEN) ------
__global__ __launch_bounds__(256) void k_gemm(const float* __restrict__ x,
                                              const float* __restrict__ w,
                                              const float* __restrict__ att) {
    __shared__ float2 sW[INC * 32];   // [k][lane]
    __shared__ float4 sx[32][32];     // [node][k4]
    int tid  = threadIdx.x;
    int lane = tid & 31;
    int wid  = tid >> 5;

    const float2* w2 = (const float2*)w;
    for (int i = tid; i < INC * 32; i += 256) sW[i] = w2[i];

    int nb = blockIdx.x * 32;
    const float4* x4 = (const float4*)x;
    for (int i = tid; i < 32 * 32; i += 256) {
        int node = i >> 5, k4 = i & 31;
        int n = nb + node;
        sx[node][k4] = (n < NN) ? x4[(size_t)n * 32 + k4] : make_float4(0.f, 0.f, 0.f, 0.f);
    }
    __syncthreads();

    int n0 = wid * 4;
    float a0[4] = {0.f, 0.f, 0.f, 0.f};
    float a1[4] = {0.f, 0.f, 0.f, 0.f};
    #pragma unroll 4
    for (int k4 = 0; k4 < 32; k4++) {
        float2 w0 = sW[(k4 * 4 + 0) * 32 + lane];
        float2 w1 = sW[(k4 * 4 + 1) * 32 + lane];
        float2 wv2 = sW[(k4 * 4 + 2) * 32 + lane];
        float2 w3 = sW[(k4 * 4 + 3) * 32 + lane];
        #pragma unroll
        for (int j = 0; j < 4; j++) {
            float4 xv = sx[n0 + j][k4];
            a0[j] = fmaf(xv.x, w0.x, a0[j]);  a1[j] = fmaf(xv.x, w0.y, a1[j]);
            a0[j] = fmaf(xv.y, w1.x, a0[j]);  a1[j] = fmaf(xv.y, w1.y, a1[j]);
            a0[j] = fmaf(xv.z, wv2.x, a0[j]); a1[j] = fmaf(xv.z, wv2.y, a1[j]);
            a0[j] = fmaf(xv.w, w3.x, a0[j]);  a1[j] = fmaf(xv.w, w3.y, a1[j]);
        }
    }

    float2 atL = ((const float2*)att)[lane];
    float2 atR = ((const float2*)att)[32 + lane];
    #pragma unroll
    for (int j = 0; j < 4; j++) {
        int n = nb + n0 + j;
        if (n >= NN) continue;
        ((float2*)g_h)[(size_t)n * 32 + lane] = make_float2(a0[j], a1[j]);
        float pl = a0[j] * atL.x + a1[j] * atL.y;
        float pr = a0[j] * atR.x + a1[j] * atR.y;
        #pragma unroll
        for (int o = 16; o > 0; o >>= 1) {
            pl += __shfl_down_sync(0xFFFFFFFFu, pl, o);
            pr += __shfl_down_sync(0xFFFFFFFFu, pr, o);
        }
        if (lane == 0) { g_hl[n] = pl; g_hr[n] = pr; }
    }
}

// ---------------- edge pass A: 4 edges/thread, alpha->exp + denom -----------
// (max-subtraction skipped: softmax shift-invariant; alpha bounded ~|10|)
__global__ __launch_bounds__(256) void k_edgeA(const int* __restrict__ src,
                                               const int* __restrict__ tgt) {
    int p = blockIdx.x * blockDim.x + threadIdx.x;   // pack of 4 edges
    int e0 = p * 4;
    if (e0 >= ET) return;
    int s[4], t[4];
    if (e0 < EE) {   // EE % 4 == 0: packs never straddle the boundary
        int4 s4 = ((const int4*)src)[p];
        int4 t4 = ((const int4*)tgt)[p];
        s[0] = s4.x; s[1] = s4.y; s[2] = s4.z; s[3] = s4.w;
        t[0] = t4.x; t[1] = t4.y; t[2] = t4.z; t[3] = t4.w;
    } else {
        int b = e0 - EE;
        #pragma unroll
        for (int i = 0; i < 4; i++) { s[i] = b + i; t[i] = b + i; }
    }
    float hlv[4], hrv[4];
    #pragma unroll
    for (int i = 0; i < 4; i++) hlv[i] = g_hl[t[i]];
    #pragma unroll
    for (int i = 0; i < 4; i++) hrv[i] = g_hr[s[i]];
    float av[4];
    #pragma unroll
    for (int i = 0; i < 4; i++) {
        float al = hlv[i] + hrv[i];
        al = al > 0.f ? al : NEG * al;
        av[i] = __expf(al);
    }
    ((float4*)g_alpha)[p] = make_float4(av[0], av[1], av[2], av[3]);
    #pragma unroll
    for (int i = 0; i < 4; i++) atomicAdd(g_denom + t[i], av[i]);
}

// ---------------- edge pass B: 4 edges/thread, normalize + asum -------------
__global__ __launch_bounds__(256) void k_edgeB(const int* __restrict__ src,
                                               const int* __restrict__ tgt) {
    int p = blockIdx.x * blockDim.x + threadIdx.x;
    int e0 = p * 4;
    if (e0 >= ET) return;
    int s[4], t[4];
    if (e0 < EE) {
        int4 s4 = ((const int4*)src)[p];
        int4 t4 = ((const int4*)tgt)[p];
        s[0] = s4.x; s[1] = s4.y; s[2] = s4.z; s[3] = s4.w;
        t[0] = t4.x; t[1] = t4.y; t[2] = t4.z; t[3] = t4.w;
    } else {
        int b = e0 - EE;
        #pragma unroll
        for (int i = 0; i < 4; i++) { s[i] = b + i; t[i] = b + i; }
    }
    float4 a4 = ((const float4*)g_alpha)[p];
    float av[4] = {a4.x, a4.y, a4.z, a4.w};
    float dn[4];
    #pragma unroll
    for (int i = 0; i < 4; i++) dn[i] = g_denom[t[i]];
    #pragma unroll
    for (int i = 0; i < 4; i++) av[i] = __fdividef(av[i], dn[i] + 1e-16f);
    ((float4*)g_alpha)[p] = make_float4(av[0], av[1], av[2], av[3]);
    #pragma unroll
    for (int i = 0; i < 4; i++) atomicAdd(g_asum + s[i], av[i]);
}

// ---------------- exact top-k: one radix level + tiny boundary-bin rank -----
__device__ __forceinline__ unsigned int ordkey(float f) {
    unsigned int u = __float_as_uint(f);
    return (u & 0x80000000u) ? ~u : (u | 0x80000000u);
}

__global__ __launch_bounds__(1024) void k_histA() {
    int n = blockIdx.x * 1024 + threadIdx.x;
    if (n < NN) atomicAdd(&g_h16a[ordkey(g_asum[n]) >> 16], 1u);
}

// Single-block parallel selection over the 65536-bin histogram -> p16, rem16.
__global__ __launch_bounds__(1024) void k_scan() {
    __shared__ unsigned int ss[1024];
    __shared__ unsigned int gsfx[256];
    __shared__ unsigned int hs[256];
    __shared__ unsigned int s_G, s_remG;
    const unsigned int* hist = g_h16a;
    unsigned int K = KSEL;
    int tid = threadIdx.x;

    unsigned int cs = 0;
    #pragma unroll 8
    for (int i = 0; i < 64; i++) cs += hist[tid * 64 + i];
    ss[tid] = cs;
    __syncthreads();
    if (tid < 256) gsfx[tid] = ss[4 * tid] + ss[4 * tid + 1] + ss[4 * tid + 2] + ss[4 * tid + 3];
    __syncthreads();
    #pragma unroll
    for (int off = 1; off < 256; off <<= 1) {
        unsigned int v = 0;
        if (tid < 256) { v = gsfx[tid]; if (tid + off < 256) v += gsfx[tid + off]; }
        __syncthreads();
        if (tid < 256) gsfx[tid] = v;
        __syncthreads();
    }
    if (tid < 256) {
        unsigned int S = gsfx[tid];
        unsigned int Sn = (tid < 255) ? gsfx[tid + 1] : 0u;
        if (S >= K && Sn < K) { s_G = tid; s_remG = K - Sn; }
    }
    __syncthreads();
    unsigned int G = s_G, remG = s_remG;
    if (tid < 256) hs[tid] = hist[G * 256 + tid];
    __syncthreads();
    #pragma unroll
    for (int off = 1; off < 256; off <<= 1) {
        unsigned int v = 0;
        if (tid < 256) { v = hs[tid]; if (tid + off < 256) v += hs[tid + off]; }
        __syncthreads();
        if (tid < 256) hs[tid] = v;
        __syncthreads();
    }
    if (tid < 256) {
        unsigned int S = hs[tid];
        unsigned int Sn = (tid < 255) ? hs[tid + 1] : 0u;
        if (S >= remG && Sn < remG) {
            g_p16   = (G * 256 + tid) << 16;
            g_rem16 = remG - Sn;
        }
    }
}

// Decide all nodes outside the boundary bin; append boundary-bin members.
__global__ __launch_bounds__(1024) void k_mark(float* __restrict__ nmask, int wm) {
    int n = blockIdx.x * 1024 + threadIdx.x;
    bool valid = n < NN;
    unsigned int p = g_p16;
    unsigned int u = valid ? ordkey(g_asum[n]) : 0u;
    bool sel  = valid && (u & 0xFFFF0000u) > p;
    bool cand = valid && (u & 0xFFFF0000u) == p;
    if (valid && !cand) {
        g_mask[n] = sel ? 1 : 0;
        if (wm) nmask[n] = sel ? 1.f : 0.f;
    }
    unsigned int amask = __activemask();
    unsigned int bal = __ballot_sync(amask, cand);
    if (bal) {
        int lane = threadIdx.x & 31;
        int leader = __ffs(bal) - 1;
        unsigned int base = 0;
        if (lane == leader) base = atomicAdd(&g_cand_n, (unsigned int)__popc(bal));
        base = __shfl_sync(amask, base, leader);
        if (cand) {
            unsigned int pos = base + __popc(bal & ((1u << lane) - 1u));
            g_ck[pos] = u;
            g_ci[pos] = n;
        }
    }
}

// Exact stable rank of boundary-bin candidates (key desc, index asc).
__global__ __launch_bounds__(256) void k_tiny(float* __restrict__ nmask, int wm) {
    int nc = (int)g_cand_n;
    unsigned int need = g_rem16;
    for (int i = threadIdx.x; i < nc; i += 256) {
        unsigned int ki = g_ck[i];
        int ii = g_ci[i];
        unsigned int rank = 0;
        for (int j = 0; j < nc; j++) {
            unsigned int kj = __ldg(&g_ck[j]);
            int ij = __ldg(&g_ci[j]);
            rank += (kj > ki) || (kj == ki && ij < ii);
        }
        bool sel = rank < need;
        g_mask[ii] = sel ? 1 : 0;
        if (wm) nmask[ii] = sel ? 1.f : 0.f;
    }
}

// ---------------- aggregation: out[t] += alpha * h[s] (R8-proven) -----------
__global__ __launch_bounds__(256) void k_aggr(const int* __restrict__ src,
                                              const int* __restrict__ tgt,
                                              float* __restrict__ out,
                                              float* __restrict__ emask, int wm) {
    int e = blockIdx.x * 16 + (threadIdx.x >> 4);
    if (e >= ET) return;
    int l = threadIdx.x & 15;
    int s, t;
    if (e < EE) { s = src[e]; t = tgt[e]; } else { s = t = e - EE; }
    bool keep = g_mask[s] && g_mask[t];
    if (wm && l == 0) emask[e] = keep ? 1.f : 0.f;
    if (!keep) return;
    float an = g_alpha[e];
    float4 hv = ((const float4*)g_h)[(size_t)s * 16 + l];
    float* dst = out + (size_t)t * OUTC + l * 4;
    asm volatile("red.global.add.v4.f32 [%0], {%1, %2, %3, %4};"
                 :: "l"(dst), "f"(an * hv.x), "f"(an * hv.y),
                    "f"(an * hv.z), "f"(an * hv.w)
                 : "memory");
}

// ---------------- launch ----------------------------------------------------
extern "C" void kernel_launch(void* const* d_in, const int* in_sizes, int n_in,
                              void* d_out, int out_size) {
    const float* x   = (const float*)d_in[0];   // [NN, INC]
    const float* w   = (const float*)d_in[1];   // [INC, OUTC]
    const float* att = (const float*)d_in[2];   // [1, 2*OUTC]
    const int*   ei  = (const int*)d_in[3];     // [2, EE]
    const int*   src = ei;
    const int*   tgt = ei + EE;
    float* out = (float*)d_out;

    int wm = (out_size >= NN * OUTC + ET + NN) ? 1 : 0;
    float* emask = out + NN * OUTC;
    float* nmask = emask + ET;

    k_init0<<<1024, 256>>>(out);     // 1st launch
    k_init1<<<256, 256>>>();         // 2nd
    k_init2<<<256, 256>>>();         // 3rd
    k_gemm<<<(NN + 31) / 32, 256>>>(x, w, att);   // 4th = ncu capture slot
    int pb = (ET / 4 + 255) / 256;
    k_edgeA<<<pb, 256>>>(src, tgt);
    k_edgeB<<<pb, 256>>>(src, tgt);
    k_histA<<<NB, 1024>>>();
    k_scan<<<1, 1024>>>();
    k_mark<<<NB, 1024>>>(nmask, wm);
    k_tiny<<<1, 256>>>(nmask, wm);
    k_aggr<<<(ET + 15) / 16, 256>>>(src, tgt, out, emask, wm);
}